// round 14
// baseline (speedup 1.0000x reference)
#include <cuda_runtime.h>
#include <cuda_fp16.h>
#include <cstdint>
#include <cstddef>

#define Bb 512
#define Tt 512
#define Ff 128
#define Uu 256
#define G4 1024   // 4*U

// ---------------- device scratch ----------------
__device__ float g_xz[(size_t)Bb * Tt * G4];          // precomputed x@kernel+bias
__device__ __half g_hv[2][Bb][Uu];                    // h (fp16), double buffered
__device__ unsigned g_barA[16][32];                   // per-group barrier, half A
__device__ unsigned g_barB[16][32];                   // per-group barrier, half B

__global__ void reset_kernel() {
    int i = blockIdx.x * blockDim.x + threadIdx.x;
    if (i < Bb * Uu) (&g_hv[0][0][0])[i] = __ushort_as_half(0);
    if (i < 16) { g_barA[i][0] = 8u; g_barB[i][0] = 8u; }   // pre-arrived for h(0)=0
}

// ---------------- helpers ----------------
__device__ __forceinline__ void mma_f16(float& d0, float& d1, float& d2, float& d3,
                                        unsigned a0, unsigned a1, unsigned a2, unsigned a3,
                                        unsigned b0, unsigned b1) {
    asm volatile("mma.sync.aligned.m16n8k16.row.col.f32.f16.f16.f32 "
                 "{%0,%1,%2,%3}, {%4,%5,%6,%7}, {%8,%9}, {%0,%1,%2,%3};"
                 : "+f"(d0), "+f"(d1), "+f"(d2), "+f"(d3)
                 : "r"(a0), "r"(a1), "r"(a2), "r"(a3), "r"(b0), "r"(b1));
}
__device__ __forceinline__ unsigned pk2(__half x, __half y) {
    __half2 t; t.x = x; t.y = y;
    return *reinterpret_cast<unsigned*>(&t);
}
__device__ __forceinline__ void cp_async16(void* sdst, const void* gsrc) {
    unsigned sa = (unsigned)__cvta_generic_to_shared(sdst);
    asm volatile("cp.async.cg.shared.global [%0], [%1], 16;" :: "r"(sa), "l"(gsrc));
}
__device__ __forceinline__ void ldsm4(unsigned& r0, unsigned& r1, unsigned& r2, unsigned& r3,
                                      const void* p) {
    unsigned sa = (unsigned)__cvta_generic_to_shared(p);
    asm volatile("ldmatrix.sync.aligned.m8n8.x4.shared.b16 {%0,%1,%2,%3}, [%4];"
                 : "=r"(r0), "=r"(r1), "=r"(r2), "=r"(r3) : "r"(sa));
}

// ================= Phase 1: XZ = x @ kernel + bias (fp16 1-pass mma) =================
#define P1_STR 136

__global__ __launch_bounds__(512, 2) void xz_gemm(const float* __restrict__ x,
                                                  const float* __restrict__ wk,
                                                  const float* __restrict__ bias) {
    extern __shared__ char smc[];
    __half* Ax  = (__half*)smc;                        // [128][136]
    __half* Bx  = (__half*)(smc + 34816);              // [64 n][136 k]

    int tid  = threadIdx.x;
    int nblk = blockIdx.x, mblk = blockIdx.y;
    const float* xblk = x + (size_t)mblk * 128 * Ff;
    const float* wcol = wk + (size_t)nblk * 64;

    {
        int r = tid >> 2, q = tid & 3;
        const float* xr = xblk + (size_t)r * Ff;
#pragma unroll
        for (int jj = 0; jj < 8; jj++) {
            int col = 4 * q + 16 * jj;
            float4 v = *(const float4*)(xr + col);
            *(unsigned*)(Ax + r * P1_STR + col)     = pk2(__float2half_rn(v.x), __float2half_rn(v.y));
            *(unsigned*)(Ax + r * P1_STR + col + 2) = pk2(__float2half_rn(v.z), __float2half_rn(v.w));
        }
    }
#pragma unroll
    for (int i = 0; i < 16; i++) {
        int flat = tid + 512 * i;
        int k = flat >> 6, n = flat & 63;
        Bx[n * P1_STR + k] = __float2half_rn(wcol[(size_t)k * G4 + n]);
    }
    __syncthreads();

    int w = tid >> 5, lane = tid & 31;
    int wm = w >> 2, wn = w & 3;
    int g = lane >> 2, tq = lane & 3;
    int mb = 32 * wm, nb = 16 * wn;

    float acc[2][2][4];
#pragma unroll
    for (int ni = 0; ni < 2; ni++) {
        float2 bv = *(const float2*)(bias + nblk * 64 + nb + 8 * ni + 2 * tq);
#pragma unroll
        for (int mi = 0; mi < 2; mi++) {
            acc[mi][ni][0] = bv.x; acc[mi][ni][1] = bv.y;
            acc[mi][ni][2] = bv.x; acc[mi][ni][3] = bv.y;
        }
    }

#pragma unroll 4
    for (int kc = 0; kc < 128; kc += 16) {
        unsigned bh[2][2];
#pragma unroll
        for (int ni = 0; ni < 2; ni++) {
            const __half* bp = Bx + (nb + 8 * ni + g) * P1_STR + kc + 2 * tq;
            bh[ni][0] = *(const unsigned*)bp;
            bh[ni][1] = *(const unsigned*)(bp + 8);
        }
#pragma unroll
        for (int mi = 0; mi < 2; mi++) {
            const __half* ap = Ax + (mb + 16 * mi + g) * P1_STR + kc + 2 * tq;
            unsigned a0 = *(const unsigned*)ap;
            unsigned a1 = *(const unsigned*)(ap + 8 * P1_STR);
            unsigned a2 = *(const unsigned*)(ap + 8);
            unsigned a3 = *(const unsigned*)(ap + 8 * P1_STR + 8);
#pragma unroll
            for (int ni = 0; ni < 2; ni++)
                mma_f16(acc[mi][ni][0], acc[mi][ni][1], acc[mi][ni][2], acc[mi][ni][3],
                        a0, a1, a2, a3, bh[ni][0], bh[ni][1]);
        }
    }

    float* od = g_xz + ((size_t)mblk * 128) * G4 + nblk * 64;
#pragma unroll
    for (int mi = 0; mi < 2; mi++) {
#pragma unroll
        for (int ni = 0; ni < 2; ni++) {
            int row = mb + 16 * mi + g, col = nb + 8 * ni + 2 * tq;
            *(float2*)(od + (size_t)row * G4 + col)       = make_float2(acc[mi][ni][0], acc[mi][ni][1]);
            *(float2*)(od + (size_t)(row + 8) * G4 + col) = make_float2(acc[mi][ni][2], acc[mi][ni][3]);
        }
    }
}

// ================= Phase 2: recurrence, half-split software pipeline =================
// 128 CTAs = 16 batch-groups x 8 col-groups. Batches split A=[0,16) B=[16,32) with
// separate barriers; h staging for one half overlaps the other half's mma/gates.
#define RC_CTAS 128
#define WS 264
#define AS 264
#define AHA_OFF 67584
#define AHB_OFF 76032
#define XS_OFF 84480
#define XSS 132
#define XSBUF (32 * XSS)
#define ZS_OFF 118272
#define ZSS 136
#define RC_SMEM 126976

__global__ __launch_bounds__(256, 1) void lstm_rec(const float* __restrict__ rk,
                                                   const float* __restrict__ dw,
                                                   const float* __restrict__ db,
                                                   float* __restrict__ out) {
    extern __shared__ char smc[];
    __half* Wh  = (__half*)smc;                        // [128][264]
    __half* AhA = (__half*)(smc + AHA_OFF);            // [16][264]
    __half* AhB = (__half*)(smc + AHB_OFF);            // [16][264]
    float* xs = (float*)(smc + XS_OFF);                // [2][32][132]
    float* zs = (float*)(smc + ZS_OFF);                // [16][136]

    int tid   = threadIdx.x;
    int bg    = blockIdx.x >> 3;
    int cg    = blockIdx.x & 7;
    int bbase = bg * 32;
    int ubase = cg * 32;

    // one-time: weight slice -> fp16, layout Wh[j][k], j = gate*32 + u
    for (int i = tid; i < 128 * 256; i += 256) {
        int j = i >> 8, k = i & 255;
        int gate = j >> 5, u = j & 31;
        Wh[j * WS + k] = __float2half_rn(rk[(size_t)k * G4 + gate * Uu + ubase + u]);
    }

    int w = tid >> 5, lane = tid & 31;
    int g = lane >> 2, tq = lane & 3;
    int nb = 16 * w;
    int gb = (tid >> 3) & 15;        // gate batch within half (tid<128 active)
    int gu = (tid & 7) * 4;
    float cstA[4] = {0.f, 0.f, 0.f, 0.f};
    float cstB[4] = {0.f, 0.f, 0.f, 0.f};

    int aRow = lane & 15;
    int aK   = (lane >> 4) * 8;
    int bRow = nb + 8 * (lane >> 4) + (lane & 7);
    int bK   = 8 * ((lane >> 3) & 1);

    volatile unsigned* ctrA = &g_barA[bg][0];
    volatile unsigned* ctrB = &g_barB[bg][0];

    // ---- bootstrap: xz(0), then AhA(0) (barA pre-armed to 8 by reset) ----
#pragma unroll
    for (int i = 0; i < 4; i++) {
        int flat4 = tid + 256 * i;
        int bbq = flat4 >> 5, rest = flat4 & 31, gg = rest >> 3, u4 = rest & 7;
        const float* gsrc = g_xz + ((size_t)(bbase + bbq) * Tt + 0) * G4 + gg * Uu + ubase + 4 * u4;
        cp_async16(xs + bbq * XSS + gg * 32 + 4 * u4, gsrc);
    }
    asm volatile("cp.async.commit_group;" ::: "memory");
    if (tid == 0) { while (*ctrA < 8u) {} __threadfence(); }
    __syncthreads();
#pragma unroll
    for (int i = 0; i < 2; i++) {
        int c = tid + 256 * i;           // 0..511 : 16 rows x 32 chunks
        int row = c >> 5, o = (c & 31) * 8;
        cp_async16(AhA + row * AS + o, &g_hv[0][bbase + row][o]);
    }
    asm volatile("cp.async.commit_group;" ::: "memory");
    // queue: [xz(0), AhA(0)]

    for (int t = 0; t < Tt; t++) {
        int cur = t & 1, nxt = cur ^ 1;
        int tn = (t + 1 < Tt) ? t + 1 : t;

        // poll barB(t), issue AhB(t)  (overlaps with upcoming mma_A)
        if (tid == 0) { unsigned tgt = 8u * t + 8u; while (*ctrB < tgt) {} __threadfence(); }
        __syncthreads();
#pragma unroll
        for (int i = 0; i < 2; i++) {
            int c = tid + 256 * i;
            int row = c >> 5, o = (c & 31) * 8;
            cp_async16(AhB + row * AS + o, &g_hv[cur][bbase + 16 + row][o]);
        }
        asm volatile("cp.async.commit_group;" ::: "memory");

        // wait xz(t) + AhA(t) (both issued >1 phase ago)
        asm volatile("cp.async.wait_group 1;" ::: "memory");
        __syncthreads();

        // ===== half A =====
        {
            float acc[2][4];
#pragma unroll
            for (int ni = 0; ni < 2; ni++) {
                const float* zp = xs + cur * XSBUF + g * XSS + nb + 8 * ni + 2 * tq;
                float2 a = *(const float2*)zp;
                float2 b = *(const float2*)(zp + 8 * XSS);
                acc[ni][0] = a.x; acc[ni][1] = a.y;
                acc[ni][2] = b.x; acc[ni][3] = b.y;
            }
#pragma unroll 4
            for (int kc = 0; kc < 256; kc += 16) {
                unsigned bh0, bh1, bh2, bh3, a0, a1, a2, a3;
                ldsm4(bh0, bh1, bh2, bh3, Wh + bRow * WS + kc + bK);
                ldsm4(a0, a1, a2, a3, AhA + aRow * AS + kc + aK);
                mma_f16(acc[0][0], acc[0][1], acc[0][2], acc[0][3], a0, a1, a2, a3, bh0, bh1);
                mma_f16(acc[1][0], acc[1][1], acc[1][2], acc[1][3], a0, a1, a2, a3, bh2, bh3);
            }
#pragma unroll
            for (int ni = 0; ni < 2; ni++) {
                float* zp = zs + g * ZSS + nb + 8 * ni + 2 * tq;
                *(float2*)zp             = make_float2(acc[ni][0], acc[ni][1]);
                *(float2*)(zp + 8 * ZSS) = make_float2(acc[ni][2], acc[ni][3]);
            }
        }
        __syncthreads();
        if (tid < 128) {
            const float* zr = zs + gb * ZSS + gu;
            float4 zi = *(const float4*)(zr + 0);
            float4 zf = *(const float4*)(zr + 32);
            float4 zg = *(const float4*)(zr + 64);
            float4 zo = *(const float4*)(zr + 96);
            float zia[4] = {zi.x, zi.y, zi.z, zi.w};
            float zfa[4] = {zf.x, zf.y, zf.z, zf.w};
            float zga[4] = {zg.x, zg.y, zg.z, zg.w};
            float zoa[4] = {zo.x, zo.y, zo.z, zo.w};
            __half hn4[4];
#pragma unroll
            for (int e = 0; e < 4; e++) {
                float ig = 1.f / (1.f + __expf(-zia[e]));
                float fg = 1.f / (1.f + __expf(-zfa[e]));
                float gg = fmaxf(zga[e], 0.f);
                float og = 1.f / (1.f + __expf(-zoa[e]));
                float cn = fg * cstA[e] + ig * gg;
                cstA[e] = cn;
                hn4[e] = __float2half_rn(og * fmaxf(cn, 0.f));
            }
            *(uint2*)(&g_hv[nxt][bbase + gb][ubase + gu]) =
                make_uint2(pk2(hn4[0], hn4[1]), pk2(hn4[2], hn4[3]));
        }
        __syncthreads();
        if (tid == 0) { __threadfence(); atomicAdd((unsigned*)ctrA, 1u); }

        // issue xz(t+1)  (overlaps with mma_B)
#pragma unroll
        for (int i = 0; i < 4; i++) {
            int flat4 = tid + 256 * i;
            int bbq = flat4 >> 5, rest = flat4 & 31, gg = rest >> 3, u4 = rest & 7;
            const float* gsrc = g_xz + ((size_t)(bbase + bbq) * Tt + tn) * G4 + gg * Uu + ubase + 4 * u4;
            cp_async16(xs + nxt * XSBUF + bbq * XSS + gg * 32 + 4 * u4, gsrc);
        }
        asm volatile("cp.async.commit_group;" ::: "memory");

        // poll barA(t+1), issue AhA(t+1)  (overlaps with mma_B)
        if (tid == 0) { unsigned tgt = 8u * t + 16u; while (*ctrA < tgt) {} __threadfence(); }
        __syncthreads();
#pragma unroll
        for (int i = 0; i < 2; i++) {
            int c = tid + 256 * i;
            int row = c >> 5, o = (c & 31) * 8;
            cp_async16(AhA + row * AS + o, &g_hv[nxt][bbase + row][o]);
        }
        asm volatile("cp.async.commit_group;" ::: "memory");

        // wait AhB(t) (issued a full A-phase ago); leaves xz(t+1), AhA(t+1) in flight
        asm volatile("cp.async.wait_group 2;" ::: "memory");
        __syncthreads();

        // ===== half B =====
        {
            float acc[2][4];
#pragma unroll
            for (int ni = 0; ni < 2; ni++) {
                const float* zp = xs + cur * XSBUF + (16 + g) * XSS + nb + 8 * ni + 2 * tq;
                float2 a = *(const float2*)zp;
                float2 b = *(const float2*)(zp + 8 * XSS);
                acc[ni][0] = a.x; acc[ni][1] = a.y;
                acc[ni][2] = b.x; acc[ni][3] = b.y;
            }
#pragma unroll 4
            for (int kc = 0; kc < 256; kc += 16) {
                unsigned bh0, bh1, bh2, bh3, a0, a1, a2, a3;
                ldsm4(bh0, bh1, bh2, bh3, Wh + bRow * WS + kc + bK);
                ldsm4(a0, a1, a2, a3, AhB + aRow * AS + kc + aK);
                mma_f16(acc[0][0], acc[0][1], acc[0][2], acc[0][3], a0, a1, a2, a3, bh0, bh1);
                mma_f16(acc[1][0], acc[1][1], acc[1][2], acc[1][3], a0, a1, a2, a3, bh2, bh3);
            }
#pragma unroll
            for (int ni = 0; ni < 2; ni++) {
                float* zp = zs + g * ZSS + nb + 8 * ni + 2 * tq;
                *(float2*)zp             = make_float2(acc[ni][0], acc[ni][1]);
                *(float2*)(zp + 8 * ZSS) = make_float2(acc[ni][2], acc[ni][3]);
            }
        }
        __syncthreads();
        if (tid < 128) {
            const float* zr = zs + gb * ZSS + gu;
            float4 zi = *(const float4*)(zr + 0);
            float4 zf = *(const float4*)(zr + 32);
            float4 zg = *(const float4*)(zr + 64);
            float4 zo = *(const float4*)(zr + 96);
            float zia[4] = {zi.x, zi.y, zi.z, zi.w};
            float zfa[4] = {zf.x, zf.y, zf.z, zf.w};
            float zga[4] = {zg.x, zg.y, zg.z, zg.w};
            float zoa[4] = {zo.x, zo.y, zo.z, zo.w};
            __half hn4[4];
#pragma unroll
            for (int e = 0; e < 4; e++) {
                float ig = 1.f / (1.f + __expf(-zia[e]));
                float fg = 1.f / (1.f + __expf(-zfa[e]));
                float gg = fmaxf(zga[e], 0.f);
                float og = 1.f / (1.f + __expf(-zoa[e]));
                float cn = fg * cstB[e] + ig * gg;
                cstB[e] = cn;
                hn4[e] = __float2half_rn(og * fmaxf(cn, 0.f));
            }
            *(uint2*)(&g_hv[nxt][bbase + 16 + gb][ubase + gu]) =
                make_uint2(pk2(hn4[0], hn4[1]), pk2(hn4[2], hn4[3]));
        }
        __syncthreads();
        if (tid == 0) { __threadfence(); atomicAdd((unsigned*)ctrB, 1u); }
    }

    // final dense: h(T) in g_hv[0] (T even). barA(T) polled in last iteration;
    // poll barB(T) here, then cg==0 computes.
    if (cg == 0) {
        if (tid == 0) { unsigned tgt = 8u * Tt + 8u; while (*ctrB < tgt) {} __threadfence(); }
        __syncthreads();
        int b = tid >> 3, r = tid & 7;
        const __half* hv = &g_hv[0][bbase + b][0];
        float s = 0.f;
#pragma unroll
        for (int j = 0; j < 32; j++) {
            int u = r + 8 * j;
            s += __half2float(hv[u]) * dw[u];
        }
        s += __shfl_down_sync(0xffffffffu, s, 4);
        s += __shfl_down_sync(0xffffffffu, s, 2);
        s += __shfl_down_sync(0xffffffffu, s, 1);
        if (r == 0) out[bbase + b] = s + db[0];
    }
}

// ---------------- launch ----------------
extern "C" void kernel_launch(void* const* d_in, const int* in_sizes, int n_in,
                              void* d_out, int out_size) {
    const float* x    = (const float*)d_in[0];
    const float* wk   = (const float*)d_in[1];
    const float* rk   = (const float*)d_in[2];
    const float* bias = (const float*)d_in[3];
    const float* dw   = (const float*)d_in[4];
    const float* db   = (const float*)d_in[5];
    float* out = (float*)d_out;

    const int smem1 = 52224;
    cudaFuncSetAttribute(xz_gemm,  cudaFuncAttributeMaxDynamicSharedMemorySize, smem1);
    cudaFuncSetAttribute(lstm_rec, cudaFuncAttributeMaxDynamicSharedMemorySize, RC_SMEM);

    reset_kernel<<<(Bb * Uu + 255) / 256, 256>>>();
    xz_gemm<<<dim3(G4 / 64, (Bb * Tt) / 128), 512, smem1>>>(x, wk, bias);
    lstm_rec<<<RC_CTAS, 256, RC_SMEM>>>(rk, dw, db, out);
}

// round 16
// speedup vs baseline: 1.5257x; 1.5257x over previous
#include <cuda_runtime.h>
#include <cuda_fp16.h>
#include <cstdint>
#include <cstddef>

#define Bb 512
#define Tt 512
#define Ff 128
#define Uu 256
#define G4 1024   // 4*U

// ---------------- device scratch ----------------
__device__ __half g_xz[(size_t)Bb * Tt * G4];         // precomputed x@kernel+bias (fp16)
__device__ __half g_hv[2][Bb][Uu];                    // h (fp16), double buffered
__device__ unsigned g_barg[32][32];                   // per-batch-group barrier (padded)

__global__ void reset_kernel() {
    int i = blockIdx.x * blockDim.x + threadIdx.x;
    if (i < Bb * Uu) (&g_hv[0][0][0])[i] = __ushort_as_half(0);
    if (i < 32 * 32) (&g_barg[0][0])[i] = 0u;
}

// ---------------- helpers ----------------
__device__ __forceinline__ void mma_f16(float& d0, float& d1, float& d2, float& d3,
                                        unsigned a0, unsigned a1, unsigned a2, unsigned a3,
                                        unsigned b0, unsigned b1) {
    asm volatile("mma.sync.aligned.m16n8k16.row.col.f32.f16.f16.f32 "
                 "{%0,%1,%2,%3}, {%4,%5,%6,%7}, {%8,%9}, {%0,%1,%2,%3};"
                 : "+f"(d0), "+f"(d1), "+f"(d2), "+f"(d3)
                 : "r"(a0), "r"(a1), "r"(a2), "r"(a3), "r"(b0), "r"(b1));
}
__device__ __forceinline__ unsigned pk2(__half x, __half y) {
    __half2 t; t.x = x; t.y = y;
    return *reinterpret_cast<unsigned*>(&t);
}
__device__ __forceinline__ void cp_async16(void* sdst, const void* gsrc) {
    unsigned sa = (unsigned)__cvta_generic_to_shared(sdst);
    asm volatile("cp.async.cg.shared.global [%0], [%1], 16;" :: "r"(sa), "l"(gsrc));
}
__device__ __forceinline__ void ldsm4(unsigned& r0, unsigned& r1, unsigned& r2, unsigned& r3,
                                      const void* p) {
    unsigned sa = (unsigned)__cvta_generic_to_shared(p);
    asm volatile("ldmatrix.sync.aligned.m8n8.x4.shared.b16 {%0,%1,%2,%3}, [%4];"
                 : "=r"(r0), "=r"(r1), "=r"(r2), "=r"(r3) : "r"(sa));
}

// ================= Phase 1: XZ = x @ kernel + bias (fp16 1-pass mma) =================
// CTA tile 128M x 64N, K=128. 512 threads = 16 warps (4x4), warp tile 32x16.
#define P1_STR 136

__global__ __launch_bounds__(512, 2) void xz_gemm(const float* __restrict__ x,
                                                  const float* __restrict__ wk,
                                                  const float* __restrict__ bias) {
    extern __shared__ char smc[];
    __half* Ax  = (__half*)smc;                        // [128][136]
    __half* Bx  = (__half*)(smc + 34816);              // [64 n][136 k]

    int tid  = threadIdx.x;
    int nblk = blockIdx.x, mblk = blockIdx.y;
    const float* xblk = x + (size_t)mblk * 128 * Ff;
    const float* wcol = wk + (size_t)nblk * 64;

    {
        int r = tid >> 2, q = tid & 3;
        const float* xr = xblk + (size_t)r * Ff;
#pragma unroll
        for (int jj = 0; jj < 8; jj++) {
            int col = 4 * q + 16 * jj;
            float4 v = *(const float4*)(xr + col);
            *(unsigned*)(Ax + r * P1_STR + col)     = pk2(__float2half_rn(v.x), __float2half_rn(v.y));
            *(unsigned*)(Ax + r * P1_STR + col + 2) = pk2(__float2half_rn(v.z), __float2half_rn(v.w));
        }
    }
#pragma unroll
    for (int i = 0; i < 16; i++) {
        int flat = tid + 512 * i;
        int k = flat >> 6, n = flat & 63;
        Bx[n * P1_STR + k] = __float2half_rn(wcol[(size_t)k * G4 + n]);
    }
    __syncthreads();

    int w = tid >> 5, lane = tid & 31;
    int wm = w >> 2, wn = w & 3;
    int g = lane >> 2, tq = lane & 3;
    int mb = 32 * wm, nb = 16 * wn;

    float acc[2][2][4];
#pragma unroll
    for (int ni = 0; ni < 2; ni++) {
        float2 bv = *(const float2*)(bias + nblk * 64 + nb + 8 * ni + 2 * tq);
#pragma unroll
        for (int mi = 0; mi < 2; mi++) {
            acc[mi][ni][0] = bv.x; acc[mi][ni][1] = bv.y;
            acc[mi][ni][2] = bv.x; acc[mi][ni][3] = bv.y;
        }
    }

#pragma unroll 4
    for (int kc = 0; kc < 128; kc += 16) {
        unsigned bh[2][2];
#pragma unroll
        for (int ni = 0; ni < 2; ni++) {
            const __half* bp = Bx + (nb + 8 * ni + g) * P1_STR + kc + 2 * tq;
            bh[ni][0] = *(const unsigned*)bp;
            bh[ni][1] = *(const unsigned*)(bp + 8);
        }
#pragma unroll
        for (int mi = 0; mi < 2; mi++) {
            const __half* ap = Ax + (mb + 16 * mi + g) * P1_STR + kc + 2 * tq;
            unsigned a0 = *(const unsigned*)ap;
            unsigned a1 = *(const unsigned*)(ap + 8 * P1_STR);
            unsigned a2 = *(const unsigned*)(ap + 8);
            unsigned a3 = *(const unsigned*)(ap + 8 * P1_STR + 8);
#pragma unroll
            for (int ni = 0; ni < 2; ni++)
                mma_f16(acc[mi][ni][0], acc[mi][ni][1], acc[mi][ni][2], acc[mi][ni][3],
                        a0, a1, a2, a3, bh[ni][0], bh[ni][1]);
        }
    }

    __half* od = g_xz + ((size_t)mblk * 128) * G4 + nblk * 64;
#pragma unroll
    for (int mi = 0; mi < 2; mi++) {
#pragma unroll
        for (int ni = 0; ni < 2; ni++) {
            int row = mb + 16 * mi + g, col = nb + 8 * ni + 2 * tq;
            *(unsigned*)(od + (size_t)row * G4 + col) =
                pk2(__float2half_rn(acc[mi][ni][0]), __float2half_rn(acc[mi][ni][1]));
            *(unsigned*)(od + (size_t)(row + 8) * G4 + col) =
                pk2(__float2half_rn(acc[mi][ni][2]), __float2half_rn(acc[mi][ni][3]));
        }
    }
}

// ================= Phase 2: recurrence (fp16 mma, 2 CTAs/SM co-residency) ==========
// 256 CTAs = 32 batch-groups(16) x 8 col-groups; 128 threads (4 warps). CTA:
// 16 batches x 128 gate-cols (j = gate*32+u). SMEM 93.4KB -> 2 CTAs/SM; the
// co-resident CTA's mma hides this CTA's h-exchange latency (R12 flow rescaled).
#define RC_CTAS 256
#define WS 264
#define AS 264
#define AH_OFF 67584
#define XS_OFF 76032
#define XSS 136                 // halves
#define XSBUF (16 * XSS)        // halves
#define ZS_OFF 84736
#define ZSS 136                 // floats
#define RC_SMEM 93440

__global__ __launch_bounds__(128, 2) void lstm_rec(const float* __restrict__ rk,
                                                   const float* __restrict__ dw,
                                                   const float* __restrict__ db,
                                                   float* __restrict__ out) {
    extern __shared__ char smc[];
    __half* Wh = (__half*)smc;                          // [128][264]
    __half* Ah = (__half*)(smc + AH_OFF);               // [16][264]
    __half* xs = (__half*)(smc + XS_OFF);               // [2][16][136]
    float*  zs = (float*)(smc + ZS_OFF);                // [16][136]

    int tid   = threadIdx.x;
    int bg    = blockIdx.x >> 3;
    int cg    = blockIdx.x & 7;
    int bbase = bg * 16;
    int ubase = cg * 32;

    // one-time: weight slice -> fp16, layout Wh[j][k], j = gate*32 + u
    for (int i = tid; i < 128 * 256; i += 128) {
        int j = i >> 8, k = i & 255;
        int gate = j >> 5, u = j & 31;
        Wh[j * WS + k] = __float2half_rn(rk[(size_t)k * G4 + gate * Uu + ubase + u]);
    }

    int w = tid >> 5, lane = tid & 31;
    int g = lane >> 2, tq = lane & 3;
    int nb = 32 * w;                 // warp covers local cols [32w,32w+32)
    int gb = tid >> 3;               // gate-layer batch (0..15)
    int gu = (tid & 7) * 4;          // gate-layer unit base
    float cst[4] = {0.f, 0.f, 0.f, 0.f};

    // t-invariant ldmatrix lane-address components
    int aRow = lane & 15;
    int aK   = (lane >> 4) * 8;
    int bRow = nb + 8 * (lane >> 4) + (lane & 7);
    int bK   = 8 * ((lane >> 3) & 1);

    volatile unsigned* ctr = &g_barg[bg][0];

    // prefetch xz(0) into xs buf 0: 16 batches x 128 cols fp16 = 256 x 16B chunks
#pragma unroll
    for (int i = 0; i < 2; i++) {
        int c = tid + 128 * i;
        int bb = c >> 4, rest = c & 15, gate = rest >> 2, q = rest & 3;
        const __half* gsrc = g_xz + ((size_t)(bbase + bb) * Tt + 0) * G4 + gate * Uu + ubase + 8 * q;
        cp_async16(xs + bb * XSS + gate * 32 + 8 * q, gsrc);
    }
    asm volatile("cp.async.commit_group;" ::: "memory");

    unsigned target = 0;

    for (int t = 0; t < Tt; t++) {
        int cur = t & 1, nxt = cur ^ 1;

        // stage h(t) tile: 16 rows x 256 halves = 512 x 16B chunks
#pragma unroll
        for (int i = 0; i < 4; i++) {
            int c = tid + 128 * i;
            int row = c >> 5, o = (c & 31) * 8;
            cp_async16(Ah + row * AS + o, &g_hv[cur][bbase + row][o]);
        }
        asm volatile("cp.async.commit_group;" ::: "memory");
        asm volatile("cp.async.wait_group 0;" ::: "memory");   // h(t) + xz(t)
        __syncthreads();

        // acc init from xz tile (fp16 -> fp32)
        float acc[4][4];
#pragma unroll
        for (int ni = 0; ni < 4; ni++) {
            const __half* zp = xs + cur * XSBUF + g * XSS + nb + 8 * ni + 2 * tq;
            float2 a = __half22float2(*(const __half2*)zp);
            float2 b = __half22float2(*(const __half2*)(zp + 8 * XSS));
            acc[ni][0] = a.x; acc[ni][1] = a.y;
            acc[ni][2] = b.x; acc[ni][3] = b.y;
        }

        // issue xz(t+1) prefetch early (hides under K-loop)
        if (t + 1 < Tt) {
#pragma unroll
            for (int i = 0; i < 2; i++) {
                int c = tid + 128 * i;
                int bb = c >> 4, rest = c & 15, gate = rest >> 2, q = rest & 3;
                const __half* gsrc = g_xz + ((size_t)(bbase + bb) * Tt + (t + 1)) * G4 + gate * Uu + ubase + 8 * q;
                cp_async16(xs + nxt * XSBUF + bb * XSS + gate * 32 + 8 * q, gsrc);
            }
            asm volatile("cp.async.commit_group;" ::: "memory");
        }

        // K loop: z += h @ Wr (fp16, ldmatrix fragments), warp tile 16x32
#pragma unroll 4
        for (int kc = 0; kc < 256; kc += 16) {
            unsigned a0, a1, a2, a3;
            ldsm4(a0, a1, a2, a3, Ah + aRow * AS + kc + aK);
            unsigned b0, b1, b2, b3;
            ldsm4(b0, b1, b2, b3, Wh + bRow * WS + kc + bK);
            mma_f16(acc[0][0], acc[0][1], acc[0][2], acc[0][3], a0, a1, a2, a3, b0, b1);
            mma_f16(acc[1][0], acc[1][1], acc[1][2], acc[1][3], a0, a1, a2, a3, b2, b3);
            unsigned c0, c1, c2, c3;
            ldsm4(c0, c1, c2, c3, Wh + (bRow + 16) * WS + kc + bK);
            mma_f16(acc[2][0], acc[2][1], acc[2][2], acc[2][3], a0, a1, a2, a3, c0, c1);
            mma_f16(acc[3][0], acc[3][1], acc[3][2], acc[3][3], a0, a1, a2, a3, c2, c3);
        }

        // bounce z through SMEM
#pragma unroll
        for (int ni = 0; ni < 4; ni++) {
            float* zp = zs + g * ZSS + nb + 8 * ni + 2 * tq;
            *(float2*)zp             = make_float2(acc[ni][0], acc[ni][1]);
            *(float2*)(zp + 8 * ZSS) = make_float2(acc[ni][2], acc[ni][3]);
        }
        __syncthreads();

        // gate layer: thread -> (batch gb, units gu..gu+3)
        {
            const float* zr = zs + gb * ZSS + gu;
            float4 zi = *(const float4*)(zr + 0);
            float4 zf = *(const float4*)(zr + 32);
            float4 zg = *(const float4*)(zr + 64);
            float4 zo = *(const float4*)(zr + 96);
            float zia[4] = {zi.x, zi.y, zi.z, zi.w};
            float zfa[4] = {zf.x, zf.y, zf.z, zf.w};
            float zga[4] = {zg.x, zg.y, zg.z, zg.w};
            float zoa[4] = {zo.x, zo.y, zo.z, zo.w};
            __half hn4[4];
#pragma unroll
            for (int e = 0; e < 4; e++) {
                float ig = 1.f / (1.f + __expf(-zia[e]));
                float fg = 1.f / (1.f + __expf(-zfa[e]));
                float gg = fmaxf(zga[e], 0.f);
                float og = 1.f / (1.f + __expf(-zoa[e]));
                float cn = fg * cst[e] + ig * gg;
                cst[e] = cn;
                hn4[e] = __float2half_rn(og * fmaxf(cn, 0.f));
            }
            *(uint2*)(&g_hv[nxt][bbase + gb][ubase + gu]) =
                make_uint2(pk2(hn4[0], hn4[1]), pk2(hn4[2], hn4[3]));
        }

        // per-batch-group barrier (8 CTAs share one counter)
        __syncthreads();
        if (tid == 0) {
            __threadfence();
            atomicAdd((unsigned*)ctr, 1u);
            target += 8;
            while (*ctr < target) { }
            __threadfence();
        }
        __syncthreads();
    }

    // final dense: out[b] = h_T[b,:] . dw + db  (T even -> final h in buffer 0)
    if (cg == 0) {
        int b = tid >> 3, r = tid & 7;
        const __half* hv = &g_hv[0][bbase + b][0];
        float s = 0.f;
#pragma unroll
        for (int j = 0; j < 32; j++) {
            int u = r + 8 * j;
            s += __half2float(hv[u]) * dw[u];
        }
        s += __shfl_down_sync(0xffffffffu, s, 4);
        s += __shfl_down_sync(0xffffffffu, s, 2);
        s += __shfl_down_sync(0xffffffffu, s, 1);
        if (r == 0) out[bbase + b] = s + db[0];
    }
}

// ---------------- launch ----------------
extern "C" void kernel_launch(void* const* d_in, const int* in_sizes, int n_in,
                              void* d_out, int out_size) {
    const float* x    = (const float*)d_in[0];
    const float* wk   = (const float*)d_in[1];
    const float* rk   = (const float*)d_in[2];
    const float* bias = (const float*)d_in[3];
    const float* dw   = (const float*)d_in[4];
    const float* db   = (const float*)d_in[5];
    float* out = (float*)d_out;

    const int smem1 = 52224;
    cudaFuncSetAttribute(xz_gemm,  cudaFuncAttributeMaxDynamicSharedMemorySize, smem1);
    cudaFuncSetAttribute(lstm_rec, cudaFuncAttributeMaxDynamicSharedMemorySize, RC_SMEM);

    reset_kernel<<<(Bb * Uu + 255) / 256, 256>>>();
    xz_gemm<<<dim3(G4 / 64, (Bb * Tt) / 128), 512, smem1>>>(x, wk, bias);
    lstm_rec<<<RC_CTAS, 128, RC_SMEM>>>(rk, dw, db, out);
}